// round 11
// baseline (speedup 1.0000x reference)
#include <cuda_runtime.h>
#include <cuda_bf16.h>
#include <cstdint>
#include <math.h>

#define B_   2
#define T_   4096
#define HID_ 2048
#define H_   16
#define D_   128
#define NC_  64      // T/CHUNK
#define CHK_ 64
#define QKVW 6144    // 3*H*D

// ---------------- scratch (static device globals; no runtime alloc) ----------------
__device__ float g_qkv[(size_t)B_ * T_ * QKVW];
__device__ float g_gate[(size_t)B_ * T_ * HID_];
__device__ float g_o[(size_t)B_ * T_ * HID_];
__device__ float g_og[(size_t)B_ * T_ * HID_];

// ================= helpers =================
__device__ __forceinline__ uint32_t smem_u32(const void* p) {
    uint32_t a;
    asm("{ .reg .u64 t; cvta.to.shared.u64 t, %1; cvt.u32.u64 %0, t; }" : "=r"(a) : "l"(p));
    return a;
}
#define CP_ASYNC16(dst, src) \
    asm volatile("cp.async.cg.shared.global [%0], [%1], 16;" \
                 :: "r"(dst), "l"(__cvta_generic_to_global(src)))
#define CP_COMMIT() asm volatile("cp.async.commit_group;" ::: "memory")
#define CP_WAIT2()  asm volatile("cp.async.wait_group 2;" ::: "memory")

__device__ __forceinline__ void mma_tf32(float* d, const uint32_t* a, const uint32_t* b) {
    asm volatile(
        "mma.sync.aligned.m16n8k8.row.col.f32.tf32.tf32.f32 "
        "{%0,%1,%2,%3}, {%4,%5,%6,%7}, {%8,%9}, {%0,%1,%2,%3};"
        : "+f"(d[0]), "+f"(d[1]), "+f"(d[2]), "+f"(d[3])
        : "r"(a[0]), "r"(a[1]), "r"(a[2]), "r"(a[3]), "r"(b[0]), "r"(b[1]));
}

// tf32 round-to-nearest on fp32 bit pattern
__device__ __forceinline__ float rtf(float x) {
    return __uint_as_float(__float_as_uint(x) + 0x1000u);
}
__device__ __forceinline__ uint32_t rtu(float x) {
    return __float_as_uint(x) + 0x1000u;
}

// ================= tf32 mma.sync NT GEMM: C[M,N] = A[M,K] * B[N,K]^T =================
// R6 configuration: block tile 128x128, BK=32, 256 threads = 8 warps (2x4),
// warp tile 64x32, scalar LDS fragment loads (proven fastest), 2 CTAs/SM.
// Single change vs R6: 3-stage cp.async pipeline (was 2).
#define GPAD  36
#define GSTGF (256 * GPAD)                 // floats per stage (A+B)
#define GSMEM (3 * GSTGF * 4)              // 110592 bytes (x2 CTAs = 221KB/SM)

__global__ __launch_bounds__(256, 2)
void gemm_mma(const float* __restrict__ A, const float* __restrict__ Bm,
              float* __restrict__ C, int M, int N, int K) {
    extern __shared__ float gsm[];
    const uint32_t sb = smem_u32(gsm);
    const int tid = threadIdx.x;
    const int lane = tid & 31, wid = tid >> 5;
    const int g = lane >> 2, c = lane & 3;
    const int bm = blockIdx.y * 128, bn = blockIdx.x * 128;
    const int wm = (wid >> 2) * 64, wn = (wid & 3) * 32;
    const int KIT = K >> 5;

    auto load_stage = [&](int s, int kt) {
        const uint32_t ab = sb + (uint32_t)s * (GSTGF * 4);
        const uint32_t bb = ab + 128 * GPAD * 4;
        const size_t kofs = (size_t)kt * 32;
#pragma unroll
        for (int i = 0; i < 4; i++) {
            int id = tid + i * 256;
            int row = id >> 3, c8 = id & 7;
            CP_ASYNC16(ab + (uint32_t)(row * (GPAD * 4) + c8 * 16),
                       A + (size_t)(bm + row) * K + kofs + c8 * 4);
        }
#pragma unroll
        for (int i = 0; i < 4; i++) {
            int id = tid + i * 256;
            int row = id >> 3, c8 = id & 7;
            CP_ASYNC16(bb + (uint32_t)(row * (GPAD * 4) + c8 * 16),
                       Bm + (size_t)(bn + row) * K + kofs + c8 * 4);
        }
    };

    float d[4][4][4];
#pragma unroll
    for (int mt = 0; mt < 4; mt++)
#pragma unroll
        for (int nt = 0; nt < 4; nt++)
#pragma unroll
            for (int i = 0; i < 4; i++) d[mt][nt][i] = 0.f;

    load_stage(0, 0); CP_COMMIT();
    load_stage(1, 1); CP_COMMIT();

    for (int it = 0; it < KIT; it++) {
        if (it + 2 < KIT) { load_stage((it + 2) % 3, it + 2); CP_COMMIT(); }
        CP_WAIT2();          // stage `it` resident; it+1, it+2 may be in flight
        __syncthreads();

        const float* As = gsm + (it % 3) * GSTGF;
        const float* Bs = As + 128 * GPAD;
#pragma unroll
        for (int k0 = 0; k0 < 4; k0++) {
            uint32_t a[4][4];
#pragma unroll
            for (int mt = 0; mt < 4; mt++) {
                const float* p = As + (wm + mt * 16 + g) * GPAD + k0 * 8 + c;
                a[mt][0] = rtu(p[0]);
                a[mt][1] = rtu(p[8 * GPAD]);
                a[mt][2] = rtu(p[4]);
                a[mt][3] = rtu(p[8 * GPAD + 4]);
            }
            uint32_t b[4][2];
#pragma unroll
            for (int nt = 0; nt < 4; nt++) {
                const float* p = Bs + (wn + nt * 8 + g) * GPAD + k0 * 8 + c;
                b[nt][0] = rtu(p[0]);
                b[nt][1] = rtu(p[4]);
            }
#pragma unroll
            for (int mt = 0; mt < 4; mt++)
#pragma unroll
                for (int nt = 0; nt < 4; nt++)
                    mma_tf32(d[mt][nt], a[mt], b[nt]);
        }
        __syncthreads();     // protect stage (it+3)%3 == it%3 from next issue
    }

#pragma unroll
    for (int mt = 0; mt < 4; mt++) {
        const int r0 = bm + wm + mt * 16 + g;
#pragma unroll
        for (int nt = 0; nt < 4; nt++) {
            const int c0 = bn + wn + nt * 8 + 2 * c;
            *(float2*)&C[(size_t)r0 * N + c0]       = make_float2(d[mt][nt][0], d[mt][nt][1]);
            *(float2*)&C[(size_t)(r0 + 8) * N + c0] = make_float2(d[mt][nt][2], d[mt][nt][3]);
        }
    }
}

// ---------------- q/k rmsnorm + RoPE (+ q * D^-0.5), in place on g_qkv ----------------
__global__ __launch_bounds__(256)
void prep_qk(float* __restrict__ qkv, const float* __restrict__ qw,
             const float* __restrict__ kw, const int* __restrict__ pos_ids) {
    const int bt = blockIdx.x;
    const int lane = threadIdx.x & 31;
    const int warp = threadIdx.x >> 5;
    const float pos = (float)pos_ids[bt];
    const float invf = expf(-(float)lane * (logf(10000.0f) / 32.0f));
    const float fr = pos * invf;
    const float cs = cosf(fr), sn = sinf(fr);

    for (int r = warp; r < 32; r += 8) {
        const int hh = r >> 1;
        const int isK = r & 1;
        float* row = qkv + (size_t)bt * QKVW + isK * (H_ * D_) + hh * D_;
        const float* w = isK ? kw : qw;
        float v0 = row[lane], v1 = row[lane + 32], v2 = row[lane + 64], v3 = row[lane + 96];
        float ss = v0 * v0 + v1 * v1 + v2 * v2 + v3 * v3;
#pragma unroll
        for (int o = 16; o; o >>= 1) ss += __shfl_xor_sync(0xFFFFFFFFu, ss, o);
        const float rs = rsqrtf(ss * (1.f / 128.f) + 1e-6f);
        v0 = v0 * rs * w[lane];      v1 = v1 * rs * w[lane + 32];
        v2 = v2 * rs * w[lane + 64]; v3 = v3 * rs * w[lane + 96];
        float nv0 = v0 * cs - v1 * sn;
        float nv1 = v1 * cs + v0 * sn;
        v0 = nv0; v1 = nv1;
        if (!isK) {
            const float sc = 0.08838834764831845f;
            v0 *= sc; v1 *= sc; v2 *= sc; v3 *= sc;
        }
        row[lane] = v0; row[lane + 32] = v1; row[lane + 64] = v2; row[lane + 96] = v3;
    }
}

// ================= chunked GLA with tf32 mma.sync tensor cores =================
#define QS 132   // sQ/sK row stride (floats)
#define VS 36    // sV/sS row stride
#define AS 68    // sAtt row stride
#define GLA_SMEM_FLOATS (64*QS + 64*QS + 64*VS + 128*VS + 64*AS + 80)

__global__ __launch_bounds__(256, 1)
void gla_kernel(const float* __restrict__ qkv, float* __restrict__ o_out) {
    extern __shared__ float sm[];
    float* sQ   = sm;                  // [64][QS]
    float* sK   = sQ + 64 * QS;        // [64][QS]
    float* sV   = sK + 64 * QS;        // [64][VS]
    float* sS   = sV + 64 * VS;        // [128][VS]
    float* sAtt = sS + 128 * VS;       // [64][AS]
    float* expg = sAtt + 64 * AS;      // [80]

    const int tid = threadIdx.x;
    const int lane = tid & 31, w = tid >> 5;
    const int g = lane >> 2, c = lane & 3;
    const int gs = blockIdx.x;
    const int h  = blockIdx.y;
    const int b  = blockIdx.z;

    float gg;
    {
        const double scale = 1.0 - 11.0 / 31.0 + 1e-5;
        const double sl = pow(2.0, -0.5 * (double)(h + 1));
        gg = (float)(-sl * scale);
    }
    if (tid <= 64) expg[tid] = expf(gg * (float)tid);
    for (int i = tid; i < 128 * VS; i += 256) sS[i] = 0.f;

    float fs[4][4];
#pragma unroll
    for (int nt = 0; nt < 4; nt++)
#pragma unroll
        for (int i = 0; i < 4; i++) fs[nt][i] = 0.f;

    __syncthreads();
    const float chdec = expg[64];

    const float* qb = qkv + (size_t)b * T_ * QKVW + h * D_;
    const int dvb = gs * 32;

    const int a_mq = (w >> 1) * 16;
    const int a_ne = (w & 1) * 32;
    const int o_mo = (w >> 1) * 16;
    const int o_no = (w & 1) * 16;
    const int s_m0 = w * 16;

    for (int ck = 0; ck < NC_; ck++) {
        const float* crow = qb + (size_t)ck * CHK_ * QKVW;
        for (int f = tid; f < 64 * 32; f += 256) {
            int r = f >> 5;
            int d4 = (f & 31) << 2;
            float4 qv = *(const float4*)(crow + (size_t)r * QKVW + d4);
            sQ[r * QS + d4 + 0] = rtf(qv.x); sQ[r * QS + d4 + 1] = rtf(qv.y);
            sQ[r * QS + d4 + 2] = rtf(qv.z); sQ[r * QS + d4 + 3] = rtf(qv.w);
            float4 kv = *(const float4*)(crow + (size_t)r * QKVW + 2048 + d4);
            sK[r * QS + d4 + 0] = rtf(kv.x); sK[r * QS + d4 + 1] = rtf(kv.y);
            sK[r * QS + d4 + 2] = rtf(kv.z); sK[r * QS + d4 + 3] = rtf(kv.w);
        }
        for (int f = tid; f < 64 * 8; f += 256) {
            int r = f >> 3;
            int d4 = (f & 7) << 2;
            float4 vv = *(const float4*)(crow + (size_t)r * QKVW + 4096 + dvb + d4);
            sV[r * VS + d4 + 0] = rtf(vv.x); sV[r * VS + d4 + 1] = rtf(vv.y);
            sV[r * VS + d4 + 2] = rtf(vv.z); sV[r * VS + d4 + 3] = rtf(vv.w);
        }
        __syncthreads();

        // ---- att = Q @ K^T (64x64, k=128), mask+decay -> sAtt (rounded) ----
        {
            float fa[4][4];
#pragma unroll
            for (int nt = 0; nt < 4; nt++)
#pragma unroll
                for (int i = 0; i < 4; i++) fa[nt][i] = 0.f;
#pragma unroll
            for (int k0 = 0; k0 < 16; k0++) {
                uint32_t a[4];
                const float* pa = sQ + (a_mq + g) * QS + k0 * 8 + c;
                a[0] = __float_as_uint(pa[0]);
                a[1] = __float_as_uint(pa[8 * QS]);
                a[2] = __float_as_uint(pa[4]);
                a[3] = __float_as_uint(pa[8 * QS + 4]);
#pragma unroll
                for (int nt = 0; nt < 4; nt++) {
                    uint32_t bb[2];
                    const float* pb = sK + (a_ne + nt * 8 + g) * QS + k0 * 8 + c;
                    bb[0] = __float_as_uint(pb[0]);
                    bb[1] = __float_as_uint(pb[4]);
                    mma_tf32(fa[nt], a, bb);
                }
            }
#pragma unroll
            for (int nt = 0; nt < 4; nt++) {
                const int e0 = a_ne + nt * 8 + 2 * c;
                const int r0 = a_mq + g, r1 = a_mq + g + 8;
                float v;
                v = (r0 >= e0)     ? fa[nt][0] * expg[r0 - e0]     : 0.f;
                sAtt[r0 * AS + e0]     = rtf(v);
                v = (r0 >= e0 + 1) ? fa[nt][1] * expg[r0 - e0 - 1] : 0.f;
                sAtt[r0 * AS + e0 + 1] = rtf(v);
                v = (r1 >= e0)     ? fa[nt][2] * expg[r1 - e0]     : 0.f;
                sAtt[r1 * AS + e0]     = rtf(v);
                v = (r1 >= e0 + 1) ? fa[nt][3] * expg[r1 - e0 - 1] : 0.f;
                sAtt[r1 * AS + e0 + 1] = rtf(v);
            }
        }
        __syncthreads();

        // ---- o = att @ V + qdec * (Q @ S_prev)  (64x32) -> gmem ----
        {
            float fi[2][4], fr[2][4];
#pragma unroll
            for (int nt = 0; nt < 2; nt++)
#pragma unroll
                for (int i = 0; i < 4; i++) { fi[nt][i] = 0.f; fr[nt][i] = 0.f; }
#pragma unroll
            for (int k0 = 0; k0 < 8; k0++) {          // intra, k over e
                uint32_t a[4];
                const float* pa = sAtt + (o_mo + g) * AS + k0 * 8 + c;
                a[0] = __float_as_uint(pa[0]);
                a[1] = __float_as_uint(pa[8 * AS]);
                a[2] = __float_as_uint(pa[4]);
                a[3] = __float_as_uint(pa[8 * AS + 4]);
#pragma unroll
                for (int nt = 0; nt < 2; nt++) {
                    uint32_t bb[2];
                    bb[0] = __float_as_uint(sV[(k0 * 8 + c) * VS + o_no + nt * 8 + g]);
                    bb[1] = __float_as_uint(sV[(k0 * 8 + c + 4) * VS + o_no + nt * 8 + g]);
                    mma_tf32(fi[nt], a, bb);
                }
            }
#pragma unroll
            for (int k0 = 0; k0 < 16; k0++) {         // inter, k over d
                uint32_t a[4];
                const float* pa = sQ + (o_mo + g) * QS + k0 * 8 + c;
                a[0] = __float_as_uint(pa[0]);
                a[1] = __float_as_uint(pa[8 * QS]);
                a[2] = __float_as_uint(pa[4]);
                a[3] = __float_as_uint(pa[8 * QS + 4]);
#pragma unroll
                for (int nt = 0; nt < 2; nt++) {
                    uint32_t bb[2];
                    bb[0] = __float_as_uint(sS[(k0 * 8 + c) * VS + o_no + nt * 8 + g]);
                    bb[1] = __float_as_uint(sS[(k0 * 8 + c + 4) * VS + o_no + nt * 8 + g]);
                    mma_tf32(fr[nt], a, bb);
                }
            }
            const int r0 = o_mo + g, r1 = o_mo + g + 8;
            const float qd0 = expg[r0 + 1], qd1 = expg[r1 + 1];
            const size_t obase = ((size_t)b * T_ + (size_t)ck * CHK_) * HID_ + h * D_ + dvb;
#pragma unroll
            for (int nt = 0; nt < 2; nt++) {
                const int col = o_no + nt * 8 + 2 * c;
                *(float2*)(o_out + obase + (size_t)r0 * HID_ + col) =
                    make_float2(fi[nt][0] + qd0 * fr[nt][0], fi[nt][1] + qd0 * fr[nt][1]);
                *(float2*)(o_out + obase + (size_t)r1 * HID_ + col) =
                    make_float2(fi[nt][2] + qd1 * fr[nt][2], fi[nt][3] + qd1 * fr[nt][3]);
            }
        }

        // ---- state: fs = chdec*fs + (kdec*K)^T @ V   (128x32, k=64) ----
        {
#pragma unroll
            for (int nt = 0; nt < 4; nt++)
#pragma unroll
                for (int i = 0; i < 4; i++) fs[nt][i] *= chdec;
#pragma unroll
            for (int k0 = 0; k0 < 8; k0++) {
                const float kd0 = expg[63 - (k0 * 8 + c)];
                const float kd1 = expg[63 - (k0 * 8 + c + 4)];
                uint32_t a[4];
                a[0] = rtu(sK[(k0 * 8 + c) * QS + s_m0 + g] * kd0);
                a[1] = rtu(sK[(k0 * 8 + c) * QS + s_m0 + g + 8] * kd0);
                a[2] = rtu(sK[(k0 * 8 + c + 4) * QS + s_m0 + g] * kd1);
                a[3] = rtu(sK[(k0 * 8 + c + 4) * QS + s_m0 + g + 8] * kd1);
#pragma unroll
                for (int nt = 0; nt < 4; nt++) {
                    uint32_t bb[2];
                    bb[0] = __float_as_uint(sV[(k0 * 8 + c) * VS + nt * 8 + g]);
                    bb[1] = __float_as_uint(sV[(k0 * 8 + c + 4) * VS + nt * 8 + g]);
                    mma_tf32(fs[nt], a, bb);
                }
            }
        }
        __syncthreads();

        // mirror state frags to sS (tf32-rounded) for next chunk's q@S
        {
            const int r0 = s_m0 + g, r1 = s_m0 + g + 8;
#pragma unroll
            for (int nt = 0; nt < 4; nt++) {
                const int col = nt * 8 + 2 * c;
                sS[r0 * VS + col]     = rtf(fs[nt][0]);
                sS[r0 * VS + col + 1] = rtf(fs[nt][1]);
                sS[r1 * VS + col]     = rtf(fs[nt][2]);
                sS[r1 * VS + col + 1] = rtf(fs[nt][3]);
            }
        }
    }
}

// ---------------- group rmsnorm * sigmoid(gate) ----------------
__global__ __launch_bounds__(256)
void epilogue_k(const float* __restrict__ o_in, const float* __restrict__ gate,
                const float* __restrict__ gw, float* __restrict__ og) {
    const int bt = blockIdx.x;
    const int lane = threadIdx.x & 31;
    const int warp = threadIdx.x >> 5;
    for (int hh = warp; hh < H_; hh += 8) {
        const size_t base = (size_t)bt * HID_ + hh * D_;
        const float* row = o_in + base;
        float v0 = row[lane], v1 = row[lane + 32], v2 = row[lane + 64], v3 = row[lane + 96];
        float ss = v0 * v0 + v1 * v1 + v2 * v2 + v3 * v3;
#pragma unroll
        for (int o = 16; o; o >>= 1) ss += __shfl_xor_sync(0xFFFFFFFFu, ss, o);
        const float rs = rsqrtf(ss * (1.f / 128.f) + 1e-6f);
        const float* gr = gate + base;
        float* out = og + base;
#pragma unroll
        for (int i = 0; i < 4; i++) {
            const int d = lane + 32 * i;
            float v = (i == 0) ? v0 : (i == 1) ? v1 : (i == 2) ? v2 : v3;
            float sg = 1.f / (1.f + expf(-gr[d]));
            out[d] = v * rs * gw[hh * D_ + d] * sg;
        }
    }
}

// ---------------- launch ----------------
extern "C" void kernel_launch(void* const* d_in, const int* in_sizes, int n_in,
                              void* d_out, int out_size) {
    const float* hidden   = (const float*)d_in[0];
    const float* w_qkv    = (const float*)d_in[1];
    const float* q_ln_w   = (const float*)d_in[2];
    const float* k_ln_w   = (const float*)d_in[3];
    const float* g_norm_w = (const float*)d_in[4];
    const float* w_g_proj = (const float*)d_in[5];
    const float* w_dense  = (const float*)d_in[6];
    const int*   pos_ids  = (const int*)d_in[7];
    float* out = (float*)d_out;

    float *qkv_p, *gate_p, *o_p, *og_p;
    cudaGetSymbolAddress((void**)&qkv_p, g_qkv);
    cudaGetSymbolAddress((void**)&gate_p, g_gate);
    cudaGetSymbolAddress((void**)&o_p, g_o);
    cudaGetSymbolAddress((void**)&og_p, g_og);

    const int M = B_ * T_;
    cudaFuncSetAttribute(gla_kernel, cudaFuncAttributeMaxDynamicSharedMemorySize,
                         GLA_SMEM_FLOATS * (int)sizeof(float));
    cudaFuncSetAttribute(gemm_mma, cudaFuncAttributeMaxDynamicSharedMemorySize, GSMEM);

    // 1) qkv projection (R6 GEMM + 3-stage pipeline)
    gemm_mma<<<dim3(QKVW / 128, M / 128), 256, GSMEM>>>(hidden, w_qkv, qkv_p, M, QKVW, HID_);
    // 2) gate projection
    gemm_mma<<<dim3(HID_ / 128, M / 128), 256, GSMEM>>>(hidden, w_g_proj, gate_p, M, HID_, HID_);
    // 3) rmsnorm + rope on q,k
    prep_qk<<<M, 256>>>(qkv_p, q_ln_w, k_ln_w, pos_ids);
    // 4) chunked gated linear attention (tf32 tensor cores)
    gla_kernel<<<dim3(4, H_, B_), 256, GLA_SMEM_FLOATS * sizeof(float)>>>(qkv_p, o_p);
    // 5) group rmsnorm * sigmoid gate
    epilogue_k<<<M, 256>>>(o_p, gate_p, g_norm_w, og_p);
    // 6) dense output projection
    gemm_mma<<<dim3(HID_ / 128, M / 128), 256, GSMEM>>>(og_p, w_dense, out, M, HID_, HID_);
}

// round 13
// speedup vs baseline: 1.4604x; 1.4604x over previous
#include <cuda_runtime.h>
#include <cuda_bf16.h>
#include <cstdint>
#include <math.h>

#define B_   2
#define T_   4096
#define HID_ 2048
#define H_   16
#define D_   128
#define NC_  64      // T/CHUNK
#define CHK_ 64
#define QKVW 6144    // 3*H*D

// ---------------- scratch (static device globals; no runtime alloc) ----------------
__device__ float g_qkv[(size_t)B_ * T_ * QKVW];
__device__ float g_gate[(size_t)B_ * T_ * HID_];
__device__ float g_o[(size_t)B_ * T_ * HID_];
__device__ float g_og[(size_t)B_ * T_ * HID_];

// ================= helpers =================
__device__ __forceinline__ uint32_t smem_u32(const void* p) {
    uint32_t a;
    asm("{ .reg .u64 t; cvta.to.shared.u64 t, %1; cvt.u32.u64 %0, t; }" : "=r"(a) : "l"(p));
    return a;
}
#define CP_ASYNC16(dst, src) \
    asm volatile("cp.async.cg.shared.global [%0], [%1], 16;" \
                 :: "r"(dst), "l"(__cvta_generic_to_global(src)))
#define CP_COMMIT() asm volatile("cp.async.commit_group;" ::: "memory")
#define CP_WAIT1()  asm volatile("cp.async.wait_group 1;" ::: "memory")

__device__ __forceinline__ void mma_tf32(float* d, const uint32_t* a, const uint32_t* b) {
    asm volatile(
        "mma.sync.aligned.m16n8k8.row.col.f32.tf32.tf32.f32 "
        "{%0,%1,%2,%3}, {%4,%5,%6,%7}, {%8,%9}, {%0,%1,%2,%3};"
        : "+f"(d[0]), "+f"(d[1]), "+f"(d[2]), "+f"(d[3])
        : "r"(a[0]), "r"(a[1]), "r"(a[2]), "r"(a[3]), "r"(b[0]), "r"(b[1]));
}

// tf32 round-to-nearest on fp32 bit pattern
__device__ __forceinline__ float rtf(float x) {
    return __uint_as_float(__float_as_uint(x) + 0x1000u);
}
__device__ __forceinline__ uint32_t rtu(float x) {
    return __float_as_uint(x) + 0x1000u;
}

// ================= tf32 mma.sync NT GEMM: C[M,N] = A[M,K] * B[N,K]^T =================
// EXACT R6 config (best measured): block tile 128x128, BK=32, 256 threads = 8 warps
// (2x4), warp tile 64x32, scalar LDS fragment loads, 2-stage cp.async, 2 CTAs/SM.
#define GPAD  36
#define GSTGF (256 * GPAD)                 // floats per stage (A+B)
#define GSMEM (2 * GSTGF * 4)              // 73728 bytes

__global__ __launch_bounds__(256, 2)
void gemm_mma(const float* __restrict__ A, const float* __restrict__ Bm,
              float* __restrict__ C, int M, int N, int K) {
    extern __shared__ float gsm[];
    const uint32_t sb = smem_u32(gsm);
    const int tid = threadIdx.x;
    const int lane = tid & 31, wid = tid >> 5;
    const int g = lane >> 2, c = lane & 3;
    const int bm = blockIdx.y * 128, bn = blockIdx.x * 128;
    const int wm = (wid >> 2) * 64, wn = (wid & 3) * 32;
    const int KIT = K >> 5;

    auto load_stage = [&](int s, int kt) {
        const uint32_t ab = sb + (uint32_t)s * (GSTGF * 4);
        const uint32_t bb = ab + 128 * GPAD * 4;
        const size_t kofs = (size_t)kt * 32;
#pragma unroll
        for (int i = 0; i < 4; i++) {
            int id = tid + i * 256;
            int row = id >> 3, c8 = id & 7;
            CP_ASYNC16(ab + (uint32_t)(row * (GPAD * 4) + c8 * 16),
                       A + (size_t)(bm + row) * K + kofs + c8 * 4);
        }
#pragma unroll
        for (int i = 0; i < 4; i++) {
            int id = tid + i * 256;
            int row = id >> 3, c8 = id & 7;
            CP_ASYNC16(bb + (uint32_t)(row * (GPAD * 4) + c8 * 16),
                       Bm + (size_t)(bn + row) * K + kofs + c8 * 4);
        }
    };

    float d[4][4][4];
#pragma unroll
    for (int mt = 0; mt < 4; mt++)
#pragma unroll
        for (int nt = 0; nt < 4; nt++)
#pragma unroll
            for (int i = 0; i < 4; i++) d[mt][nt][i] = 0.f;

    load_stage(0, 0);
    CP_COMMIT();

    for (int it = 0; it < KIT; it++) {
        if (it + 1 < KIT) load_stage((it + 1) & 1, it + 1);
        CP_COMMIT();
        CP_WAIT1();
        __syncthreads();

        const float* As = gsm + (it & 1) * GSTGF;
        const float* Bs = As + 128 * GPAD;
#pragma unroll
        for (int k0 = 0; k0 < 4; k0++) {
            uint32_t a[4][4];
#pragma unroll
            for (int mt = 0; mt < 4; mt++) {
                const float* p = As + (wm + mt * 16 + g) * GPAD + k0 * 8 + c;
                a[mt][0] = rtu(p[0]);
                a[mt][1] = rtu(p[8 * GPAD]);
                a[mt][2] = rtu(p[4]);
                a[mt][3] = rtu(p[8 * GPAD + 4]);
            }
            uint32_t b[4][2];
#pragma unroll
            for (int nt = 0; nt < 4; nt++) {
                const float* p = Bs + (wn + nt * 8 + g) * GPAD + k0 * 8 + c;
                b[nt][0] = rtu(p[0]);
                b[nt][1] = rtu(p[4]);
            }
#pragma unroll
            for (int mt = 0; mt < 4; mt++)
#pragma unroll
                for (int nt = 0; nt < 4; nt++)
                    mma_tf32(d[mt][nt], a[mt], b[nt]);
        }
        __syncthreads();
    }

#pragma unroll
    for (int mt = 0; mt < 4; mt++) {
        const int r0 = bm + wm + mt * 16 + g;
#pragma unroll
        for (int nt = 0; nt < 4; nt++) {
            const int c0 = bn + wn + nt * 8 + 2 * c;
            *(float2*)&C[(size_t)r0 * N + c0]       = make_float2(d[mt][nt][0], d[mt][nt][1]);
            *(float2*)&C[(size_t)(r0 + 8) * N + c0] = make_float2(d[mt][nt][2], d[mt][nt][3]);
        }
    }
}

// ---------------- q/k rmsnorm + RoPE (+ q * D^-0.5), in place on g_qkv ----------------
__global__ __launch_bounds__(256)
void prep_qk(float* __restrict__ qkv, const float* __restrict__ qw,
             const float* __restrict__ kw, const int* __restrict__ pos_ids) {
    const int bt = blockIdx.x;
    const int lane = threadIdx.x & 31;
    const int warp = threadIdx.x >> 5;
    const float pos = (float)pos_ids[bt];
    const float invf = expf(-(float)lane * (logf(10000.0f) / 32.0f));
    const float fr = pos * invf;
    const float cs = cosf(fr), sn = sinf(fr);

    for (int r = warp; r < 32; r += 8) {
        const int hh = r >> 1;
        const int isK = r & 1;
        float* row = qkv + (size_t)bt * QKVW + isK * (H_ * D_) + hh * D_;
        const float* w = isK ? kw : qw;
        float v0 = row[lane], v1 = row[lane + 32], v2 = row[lane + 64], v3 = row[lane + 96];
        float ss = v0 * v0 + v1 * v1 + v2 * v2 + v3 * v3;
#pragma unroll
        for (int o = 16; o; o >>= 1) ss += __shfl_xor_sync(0xFFFFFFFFu, ss, o);
        const float rs = rsqrtf(ss * (1.f / 128.f) + 1e-6f);
        v0 = v0 * rs * w[lane];      v1 = v1 * rs * w[lane + 32];
        v2 = v2 * rs * w[lane + 64]; v3 = v3 * rs * w[lane + 96];
        float nv0 = v0 * cs - v1 * sn;
        float nv1 = v1 * cs + v0 * sn;
        v0 = nv0; v1 = nv1;
        if (!isK) {
            const float sc = 0.08838834764831845f;
            v0 *= sc; v1 *= sc; v2 *= sc; v3 *= sc;
        }
        row[lane] = v0; row[lane + 32] = v1; row[lane + 64] = v2; row[lane + 96] = v3;
    }
}

// ================= chunked GLA, tf32 mma.sync, 512 threads (16 warps) =================
// Same math/phases as the proven 256-thread version; each phase's tile grid is
// split 2x finer so per-warp serial work halves and 4 warps/SMSP hide LDS latency.
#define QS 132   // sQ/sK row stride (floats)
#define VS 36    // sV/sS row stride
#define AS 68    // sAtt row stride
#define GLA_SMEM_FLOATS (64*QS + 64*QS + 64*VS + 128*VS + 64*AS + 80)

__global__ __launch_bounds__(512, 1)
void gla_kernel(const float* __restrict__ qkv, float* __restrict__ o_out) {
    extern __shared__ float sm[];
    float* sQ   = sm;                  // [64][QS]
    float* sK   = sQ + 64 * QS;        // [64][QS]
    float* sV   = sK + 64 * QS;        // [64][VS]
    float* sS   = sV + 64 * VS;        // [128][VS]
    float* sAtt = sS + 128 * VS;       // [64][AS]
    float* expg = sAtt + 64 * AS;      // [80]

    const int tid = threadIdx.x;
    const int lane = tid & 31, w = tid >> 5;           // w = 0..15
    const int g = lane >> 2, c = lane & 3;
    const int gs = blockIdx.x;
    const int h  = blockIdx.y;
    const int b  = blockIdx.z;

    float gg;
    {
        const double scale = 1.0 - 11.0 / 31.0 + 1e-5;
        const double sl = pow(2.0, -0.5 * (double)(h + 1));
        gg = (float)(-sl * scale);
    }
    if (tid <= 64) expg[tid] = expf(gg * (float)tid);
    for (int i = tid; i < 128 * VS; i += 512) sS[i] = 0.f;

    // state: warp w owns rows [(w>>1)*16, +16) x cols [(w&1)*16, +16) -> 2 n-tiles
    float fs[2][4];
#pragma unroll
    for (int nt = 0; nt < 2; nt++)
#pragma unroll
        for (int i = 0; i < 4; i++) fs[nt][i] = 0.f;

    __syncthreads();
    const float chdec = expg[64];

    const float* qb = qkv + (size_t)b * T_ * QKVW + h * D_;
    const int dvb = gs * 32;

    const int a_mq = (w >> 2) * 16;   // att: 4 m-tiles
    const int a_ne = (w & 3) * 16;    // att: 4 col-quarters (2 n-tiles each)
    const int o_mo = (w >> 2) * 16;   // o: 4 m-tiles
    const int o_no = (w & 3) * 8;     // o: 4 col-eighths (1 n-tile each)
    const int s_m0 = (w >> 1) * 16;   // state: 8 m-tiles
    const int s_nb = (w & 1) * 16;    // state: 2 col-halves (2 n-tiles each)

    for (int ck = 0; ck < NC_; ck++) {
        const float* crow = qb + (size_t)ck * CHK_ * QKVW;
        for (int f = tid; f < 64 * 32; f += 512) {
            int r = f >> 5;
            int d4 = (f & 31) << 2;
            float4 qv = *(const float4*)(crow + (size_t)r * QKVW + d4);
            sQ[r * QS + d4 + 0] = rtf(qv.x); sQ[r * QS + d4 + 1] = rtf(qv.y);
            sQ[r * QS + d4 + 2] = rtf(qv.z); sQ[r * QS + d4 + 3] = rtf(qv.w);
            float4 kv = *(const float4*)(crow + (size_t)r * QKVW + 2048 + d4);
            sK[r * QS + d4 + 0] = rtf(kv.x); sK[r * QS + d4 + 1] = rtf(kv.y);
            sK[r * QS + d4 + 2] = rtf(kv.z); sK[r * QS + d4 + 3] = rtf(kv.w);
        }
        for (int f = tid; f < 64 * 8; f += 512) {
            int r = f >> 3;
            int d4 = (f & 7) << 2;
            float4 vv = *(const float4*)(crow + (size_t)r * QKVW + 4096 + dvb + d4);
            sV[r * VS + d4 + 0] = rtf(vv.x); sV[r * VS + d4 + 1] = rtf(vv.y);
            sV[r * VS + d4 + 2] = rtf(vv.z); sV[r * VS + d4 + 3] = rtf(vv.w);
        }
        __syncthreads();

        // ---- att = Q @ K^T (64x64, k=128), mask+decay -> sAtt (rounded) ----
        {
            float fa[2][4];
#pragma unroll
            for (int nt = 0; nt < 2; nt++)
#pragma unroll
                for (int i = 0; i < 4; i++) fa[nt][i] = 0.f;
#pragma unroll
            for (int k0 = 0; k0 < 16; k0++) {
                uint32_t a[4];
                const float* pa = sQ + (a_mq + g) * QS + k0 * 8 + c;
                a[0] = __float_as_uint(pa[0]);
                a[1] = __float_as_uint(pa[8 * QS]);
                a[2] = __float_as_uint(pa[4]);
                a[3] = __float_as_uint(pa[8 * QS + 4]);
#pragma unroll
                for (int nt = 0; nt < 2; nt++) {
                    uint32_t bb[2];
                    const float* pb = sK + (a_ne + nt * 8 + g) * QS + k0 * 8 + c;
                    bb[0] = __float_as_uint(pb[0]);
                    bb[1] = __float_as_uint(pb[4]);
                    mma_tf32(fa[nt], a, bb);
                }
            }
#pragma unroll
            for (int nt = 0; nt < 2; nt++) {
                const int e0 = a_ne + nt * 8 + 2 * c;
                const int r0 = a_mq + g, r1 = a_mq + g + 8;
                float v;
                v = (r0 >= e0)     ? fa[nt][0] * expg[r0 - e0]     : 0.f;
                sAtt[r0 * AS + e0]     = rtf(v);
                v = (r0 >= e0 + 1) ? fa[nt][1] * expg[r0 - e0 - 1] : 0.f;
                sAtt[r0 * AS + e0 + 1] = rtf(v);
                v = (r1 >= e0)     ? fa[nt][2] * expg[r1 - e0]     : 0.f;
                sAtt[r1 * AS + e0]     = rtf(v);
                v = (r1 >= e0 + 1) ? fa[nt][3] * expg[r1 - e0 - 1] : 0.f;
                sAtt[r1 * AS + e0 + 1] = rtf(v);
            }
        }
        __syncthreads();

        // ---- o = att @ V + qdec * (Q @ S_prev)  (64x32) -> gmem ----
        {
            float fi[4], fr[4];
#pragma unroll
            for (int i = 0; i < 4; i++) { fi[i] = 0.f; fr[i] = 0.f; }
#pragma unroll
            for (int k0 = 0; k0 < 8; k0++) {          // intra, k over e
                uint32_t a[4];
                const float* pa = sAtt + (o_mo + g) * AS + k0 * 8 + c;
                a[0] = __float_as_uint(pa[0]);
                a[1] = __float_as_uint(pa[8 * AS]);
                a[2] = __float_as_uint(pa[4]);
                a[3] = __float_as_uint(pa[8 * AS + 4]);
                uint32_t bb[2];
                bb[0] = __float_as_uint(sV[(k0 * 8 + c) * VS + o_no + g]);
                bb[1] = __float_as_uint(sV[(k0 * 8 + c + 4) * VS + o_no + g]);
                mma_tf32(fi, a, bb);
            }
#pragma unroll
            for (int k0 = 0; k0 < 16; k0++) {         // inter, k over d
                uint32_t a[4];
                const float* pa = sQ + (o_mo + g) * QS + k0 * 8 + c;
                a[0] = __float_as_uint(pa[0]);
                a[1] = __float_as_uint(pa[8 * QS]);
                a[2] = __float_as_uint(pa[4]);
                a[3] = __float_as_uint(pa[8 * QS + 4]);
                uint32_t bb[2];
                bb[0] = __float_as_uint(sS[(k0 * 8 + c) * VS + o_no + g]);
                bb[1] = __float_as_uint(sS[(k0 * 8 + c + 4) * VS + o_no + g]);
                mma_tf32(fr, a, bb);
            }
            const int r0 = o_mo + g, r1 = o_mo + g + 8;
            const float qd0 = expg[r0 + 1], qd1 = expg[r1 + 1];
            const size_t obase = ((size_t)b * T_ + (size_t)ck * CHK_) * HID_ + h * D_ + dvb;
            const int col = o_no + 2 * c;
            *(float2*)(o_out + obase + (size_t)r0 * HID_ + col) =
                make_float2(fi[0] + qd0 * fr[0], fi[1] + qd0 * fr[1]);
            *(float2*)(o_out + obase + (size_t)r1 * HID_ + col) =
                make_float2(fi[2] + qd1 * fr[2], fi[3] + qd1 * fr[3]);
        }

        // ---- state: fs = chdec*fs + (kdec*K)^T @ V   (128x32, k=64) ----
        {
#pragma unroll
            for (int nt = 0; nt < 2; nt++)
#pragma unroll
                for (int i = 0; i < 4; i++) fs[nt][i] *= chdec;
#pragma unroll
            for (int k0 = 0; k0 < 8; k0++) {
                const float kd0 = expg[63 - (k0 * 8 + c)];
                const float kd1 = expg[63 - (k0 * 8 + c + 4)];
                uint32_t a[4];
                a[0] = rtu(sK[(k0 * 8 + c) * QS + s_m0 + g] * kd0);
                a[1] = rtu(sK[(k0 * 8 + c) * QS + s_m0 + g + 8] * kd0);
                a[2] = rtu(sK[(k0 * 8 + c + 4) * QS + s_m0 + g] * kd1);
                a[3] = rtu(sK[(k0 * 8 + c + 4) * QS + s_m0 + g + 8] * kd1);
#pragma unroll
                for (int nt = 0; nt < 2; nt++) {
                    uint32_t bb[2];
                    bb[0] = __float_as_uint(sV[(k0 * 8 + c) * VS + s_nb + nt * 8 + g]);
                    bb[1] = __float_as_uint(sV[(k0 * 8 + c + 4) * VS + s_nb + nt * 8 + g]);
                    mma_tf32(fs[nt], a, bb);
                }
            }
        }
        __syncthreads();   // all reads of sS/sQ/sK/sV done

        // mirror state frags to sS (tf32-rounded) for next chunk's q@S
        {
            const int r0 = s_m0 + g, r1 = s_m0 + g + 8;
#pragma unroll
            for (int nt = 0; nt < 2; nt++) {
                const int col = s_nb + nt * 8 + 2 * c;
                sS[r0 * VS + col]     = rtf(fs[nt][0]);
                sS[r0 * VS + col + 1] = rtf(fs[nt][1]);
                sS[r1 * VS + col]     = rtf(fs[nt][2]);
                sS[r1 * VS + col + 1] = rtf(fs[nt][3]);
            }
        }
        // next iteration's first __syncthreads() orders these sS writes
        // before the o-phase readers.
    }
}

// ---------------- group rmsnorm * sigmoid(gate) ----------------
__global__ __launch_bounds__(256)
void epilogue_k(const float* __restrict__ o_in, const float* __restrict__ gate,
                const float* __restrict__ gw, float* __restrict__ og) {
    const int bt = blockIdx.x;
    const int lane = threadIdx.x & 31;
    const int warp = threadIdx.x >> 5;
    for (int hh = warp; hh < H_; hh += 8) {
        const size_t base = (size_t)bt * HID_ + hh * D_;
        const float* row = o_in + base;
        float v0 = row[lane], v1 = row[lane + 32], v2 = row[lane + 64], v3 = row[lane + 96];
        float ss = v0 * v0 + v1 * v1 + v2 * v2 + v3 * v3;
#pragma unroll
        for (int o = 16; o; o >>= 1) ss += __shfl_xor_sync(0xFFFFFFFFu, ss, o);
        const float rs = rsqrtf(ss * (1.f / 128.f) + 1e-6f);
        const float* gr = gate + base;
        float* out = og + base;
#pragma unroll
        for (int i = 0; i < 4; i++) {
            const int d = lane + 32 * i;
            float v = (i == 0) ? v0 : (i == 1) ? v1 : (i == 2) ? v2 : v3;
            float sg = 1.f / (1.f + expf(-gr[d]));
            out[d] = v * rs * gw[hh * D_ + d] * sg;
        }
    }
}

// ---------------- launch ----------------
extern "C" void kernel_launch(void* const* d_in, const int* in_sizes, int n_in,
                              void* d_out, int out_size) {
    const float* hidden   = (const float*)d_in[0];
    const float* w_qkv    = (const float*)d_in[1];
    const float* q_ln_w   = (const float*)d_in[2];
    const float* k_ln_w   = (const float*)d_in[3];
    const float* g_norm_w = (const float*)d_in[4];
    const float* w_g_proj = (const float*)d_in[5];
    const float* w_dense  = (const float*)d_in[6];
    const int*   pos_ids  = (const int*)d_in[7];
    float* out = (float*)d_out;

    float *qkv_p, *gate_p, *o_p, *og_p;
    cudaGetSymbolAddress((void**)&qkv_p, g_qkv);
    cudaGetSymbolAddress((void**)&gate_p, g_gate);
    cudaGetSymbolAddress((void**)&o_p, g_o);
    cudaGetSymbolAddress((void**)&og_p, g_og);

    const int M = B_ * T_;
    cudaFuncSetAttribute(gla_kernel, cudaFuncAttributeMaxDynamicSharedMemorySize,
                         GLA_SMEM_FLOATS * (int)sizeof(float));
    cudaFuncSetAttribute(gemm_mma, cudaFuncAttributeMaxDynamicSharedMemorySize, GSMEM);

    // 1) qkv projection (exact R6 GEMM)
    gemm_mma<<<dim3(QKVW / 128, M / 128), 256, GSMEM>>>(hidden, w_qkv, qkv_p, M, QKVW, HID_);
    // 2) gate projection
    gemm_mma<<<dim3(HID_ / 128, M / 128), 256, GSMEM>>>(hidden, w_g_proj, gate_p, M, HID_, HID_);
    // 3) rmsnorm + rope on q,k
    prep_qk<<<M, 256>>>(qkv_p, q_ln_w, k_ln_w, pos_ids);
    // 4) chunked gated linear attention (512 threads, 16 warps)
    gla_kernel<<<dim3(4, H_, B_), 512, GLA_SMEM_FLOATS * sizeof(float)>>>(qkv_p, o_p);
    // 5) group rmsnorm * sigmoid gate
    epilogue_k<<<M, 256>>>(o_p, gate_p, g_norm_w, og_p);
    // 6) dense output projection
    gemm_mma<<<dim3(HID_ / 128, M / 128), 256, GSMEM>>>(og_p, w_dense, out, M, HID_, HID_);
}